// round 11
// baseline (speedup 1.0000x reference)
#include <cuda_runtime.h>
#include <cuda_fp16.h>
#include <cstdint>

#define D_DIM   512
#define K_DIM   112
#define BM      128
#define NTHR    256
#define NIT     16
#define LAMBDA_ 5.0f

// ---- SMEM layout (bytes) ----
// phase 1: A stages 0..40960, B1 stages 40960..69632; sims overlay 0..58368
#define A_STRIDE   80
#define A_HALF     (BM * A_STRIDE)          // 10240
#define A_STAGE    (2 * A_HALF)             // 20480
#define B1_OFF     40960
#define B1_STAGE   14336
#define SIMSP      114
// phase 2: Wh 0..30720, Wl 30720..61440, B2 stages 61440..90112
#define W_STRIDE   240
#define WH_OFF     0
#define WL_OFF     30720
#define B2_OFF     61440
#define B2_STAGE   14336                    // 7kh x 8n8 x 32 x 8B
// shared tail
#define W5_OFF     90112
#define I5_OFF     (W5_OFF + BM * 5 * 4)
#define SMEM_BYTES (I5_OFF + BM * 5 * 4)    // 95232

// phase-1 B fragments: [kh 32][hl 2][tile 14][lane 32] uint2
__device__ __align__(16) uint2 g_bfrag[32 * 2 * 14 * 32];
// phase-2 B fragments (C hi only): [chunk 8][kh 7][n8 8][lane 32] uint2
__device__ __align__(16) uint2 g_b2[8 * 7 * 8 * 32];

__device__ __forceinline__ uint32_t smem_u32(const void* p) {
    uint32_t a;
    asm("{ .reg .u64 t; cvta.to.shared.u64 t, %1; cvt.u32.u64 %0, t; }" : "=r"(a) : "l"(p));
    return a;
}
__device__ __forceinline__ void splith(float a, float b, uint32_t& hi, uint32_t& lo) {
    __half2 h = __floats2half2_rn(a, b);
    float2  f = __half22float2(h);
    __half2 l = __floats2half2_rn(a - f.x, b - f.y);
    hi = *(uint32_t*)&h;
    lo = *(uint32_t*)&l;
}

#define LDSM4(r, addr) \
    asm volatile("ldmatrix.sync.aligned.m8n8.x4.shared.b16 {%0,%1,%2,%3}, [%4];" \
                 : "=r"((r)[0]), "=r"((r)[1]), "=r"((r)[2]), "=r"((r)[3]) : "r"(addr))
#define MMA(d, a, b0, b1) \
    asm volatile("mma.sync.aligned.m16n8k16.row.col.f32.f16.f16.f32 " \
                 "{%0,%1,%2,%3}, {%4,%5,%6,%7}, {%8,%9}, {%0,%1,%2,%3};" \
                 : "+f"((d)[0]), "+f"((d)[1]), "+f"((d)[2]), "+f"((d)[3]) \
                 : "r"((a)[0]), "r"((a)[1]), "r"((a)[2]), "r"((a)[3]), "r"(b0), "r"(b1))
#define CPASYNC16(dst, src) \
    asm volatile("cp.async.cg.shared.global [%0], [%1], 16;" :: "r"(dst), "l"(src) : "memory")
#define CP_COMMIT()  asm volatile("cp.async.commit_group;" ::: "memory")
#define CP_WAIT0()   asm volatile("cp.async.wait_group 0;" ::: "memory")

// ---- pre-kernel 1: sims-GEMM B fragments (hi/lo fp16) ----
__global__ void cc_frag_kernel(const float* __restrict__ cc) {
    int kh = blockIdx.x / 14, n8 = blockIdx.x % 14;
    int l = threadIdx.x;
    int n  = n8 * 8 + (l >> 2);
    int k0 = kh * 16 + (l & 3) * 2;
    uint32_t b0h, b0l, b1h, b1l;
    splith(cc[n * D_DIM + k0],     cc[n * D_DIM + k0 + 1], b0h, b0l);
    splith(cc[n * D_DIM + k0 + 8], cc[n * D_DIM + k0 + 9], b1h, b1l);
    g_bfrag[((kh * 2 + 0) * 14 + n8) * 32 + l] = make_uint2(b0h, b1h);
    g_bfrag[((kh * 2 + 1) * 14 + n8) * 32 + l] = make_uint2(b0l, b1l);
}

// ---- pre-kernel 2: out-GEMM B fragments: B[k=center][n=dim], fp16 hi ----
__global__ void cc_frag2_kernel(const float* __restrict__ cc) {
    int b = blockIdx.x;                       // 0..447
    int chunk = b / 56, rem = b % 56;
    int kh = rem / 8, n8 = rem % 8;
    int l = threadIdx.x;
    int d  = chunk * 64 + n8 * 8 + (l >> 2);
    int k0 = kh * 16 + (l & 3) * 2;
    __half2 h0 = __floats2half2_rn(cc[k0 * D_DIM + d],       cc[(k0 + 1) * D_DIM + d]);
    __half2 h1 = __floats2half2_rn(cc[(k0 + 8) * D_DIM + d], cc[(k0 + 9) * D_DIM + d]);
    g_b2[((chunk * 7 + kh) * 8 + n8) * 32 + l] = make_uint2(*(uint32_t*)&h0, *(uint32_t*)&h1);
}

__global__ __launch_bounds__(NTHR, 2)
void tse_hmma5_kernel(const float* __restrict__ x,
                      const float* __restrict__ cc,
                      float* __restrict__ out)
{
    extern __shared__ unsigned char smem[];
    const uint32_t sb = smem_u32(smem);
    const int tid = threadIdx.x;
    const int w   = tid >> 5;
    const int l   = tid & 31;
    const int mg  = w & 3;
    const int nh  = w >> 2;
    const int nb7 = nh * 7;
    const int row0 = blockIdx.x * BM;

    // ================= phase 1: sims GEMM =================
    float d1[2][7][4];
    #pragma unroll
    for (int m = 0; m < 2; m++)
        #pragma unroll
        for (int p = 0; p < 7; p++)
            #pragma unroll
            for (int j = 0; j < 4; j++) d1[m][p][j] = 0.0f;

    const uint32_t aOff = (uint32_t)(mg * 32 + (l & 15)) * A_STRIDE + ((l >> 4) << 4);
    const int srow0 = tid >> 3;
    const int sseg  = tid & 7;
    float4 px[4];

    auto FETCH = [&](int it) {
        #pragma unroll
        for (int i = 0; i < 4; i++)
            px[i] = *(const float4*)&x[(size_t)(row0 + srow0 + 32 * i) * D_DIM + it * 32 + sseg * 4];
    };
    auto STOREA = [&](int s) {
        unsigned char* st = smem + s * A_STAGE;
        #pragma unroll
        for (int i = 0; i < 4; i++) {
            uint32_t h0, l0, h1, l1;
            splith(px[i].x, px[i].y, h0, l0);
            splith(px[i].z, px[i].w, h1, l1);
            uint32_t off = (uint32_t)(srow0 + 32 * i) * A_STRIDE + sseg * 8;
            *(uint2*)(st + off)          = make_uint2(h0, h1);
            *(uint2*)(st + A_HALF + off) = make_uint2(l0, l1);
        }
    };
    auto CPB1 = [&](int it) {
        const char* src = (const char*)g_bfrag + (size_t)it * B1_STAGE;
        uint32_t dst = sb + B1_OFF + (it & 1) * B1_STAGE;
        #pragma unroll
        for (int i = 0; i < 4; i++) {
            int idx = tid + 256 * i;
            if (i < 3 || idx < 896)
                CPASYNC16(dst + idx * 16, src + idx * 16);
        }
        CP_COMMIT();
    };

    CPB1(0);
    FETCH(0);
    STOREA(0);

    for (int it = 0; it < NIT; it++) {
        CP_WAIT0();
        __syncthreads();
        if (it + 1 < NIT) CPB1(it + 1);
        if (it + 1 < NIT) FETCH(it + 1);

        const uint32_t aBase = sb + (it & 1) * A_STAGE + aOff;
        const uint2* Bst = (const uint2*)(smem + B1_OFF + (it & 1) * B1_STAGE);

        #pragma unroll
        for (int h = 0; h < 2; h++) {
            uint32_t ah[2][4], al[2][4];
            LDSM4(ah[0], aBase + h * 32);
            LDSM4(ah[1], aBase + 16 * A_STRIDE + h * 32);
            LDSM4(al[0], aBase + A_HALF + h * 32);
            LDSM4(al[1], aBase + A_HALF + 16 * A_STRIDE + h * 32);

            uint2 b[7];
            #pragma unroll
            for (int p = 0; p < 7; p++)
                b[p] = Bst[((h * 2 + 0) * 14 + nb7 + p) * 32 + l];
            #pragma unroll
            for (int p = 0; p < 7; p++) {
                MMA(d1[0][p], ah[0], b[p].x, b[p].y);
                MMA(d1[1][p], ah[1], b[p].x, b[p].y);
                MMA(d1[0][p], al[0], b[p].x, b[p].y);
                MMA(d1[1][p], al[1], b[p].x, b[p].y);
            }
            #pragma unroll
            for (int p = 0; p < 7; p++)
                b[p] = Bst[((h * 2 + 1) * 14 + nb7 + p) * 32 + l];
            #pragma unroll
            for (int p = 0; p < 7; p++) {
                MMA(d1[0][p], ah[0], b[p].x, b[p].y);
                MMA(d1[1][p], ah[1], b[p].x, b[p].y);
            }
        }
        if (it + 1 < NIT) STOREA((it + 1) & 1);
    }
    __syncthreads();

    // prefetch phase-2 chunk 0 early (region disjoint from sims/W/w5)
    {
        const char* src = (const char*)g_b2;
        uint32_t dst = sb + B2_OFF;
        #pragma unroll
        for (int i = 0; i < 4; i++) {
            int idx = tid + 256 * i;
            if (i < 3 || idx < 896)
                CPASYNC16(dst + idx * 16, src + idx * 16);
        }
        CP_COMMIT();
    }

    // ---- sims dump (overlay A stages) ----
    float* sims = (float*)smem;
    {
        int c0 = nh * 56 + (l & 3) * 2;
        #pragma unroll
        for (int m = 0; m < 2; m++) {
            int r1 = mg * 32 + m * 16 + (l >> 2);
            int r2 = r1 + 8;
            #pragma unroll
            for (int p = 0; p < 7; p++) {
                *(float2*)&sims[r1 * SIMSP + c0 + p * 8] = make_float2(d1[m][p][0], d1[m][p][1]);
                *(float2*)&sims[r2 * SIMSP + c0 + p * 8] = make_float2(d1[m][p][2], d1[m][p][3]);
            }
        }
    }
    __syncthreads();

    // ---- per-row top-5 + softmax (lambda folded into weights) ----
    float* w5 = (float*)(smem + W5_OFF);
    int*   i5 = (int*)(smem + I5_OFF);
    if (tid < BM) {
        const float* sr = &sims[tid * SIMSP];
        float v0 = -1e30f, v1 = -1e30f, v2 = -1e30f, v3 = -1e30f, v4 = -1e30f;
        int   i0 = 0, i1 = 0, i2 = 0, i3 = 0, i4 = 0;
        for (int c = 0; c < K_DIM; c++) {
            float s = sr[c];
            if (s > v4) {
                v4 = s; i4 = c;
                if (v4 > v3) { float t=v3; v3=v4; v4=t; int q=i3; i3=i4; i4=q; }
                if (v3 > v2) { float t=v2; v2=v3; v3=t; int q=i2; i2=i3; i3=q; }
                if (v2 > v1) { float t=v1; v1=v2; v2=t; int q=i1; i1=i2; i2=q; }
                if (v1 > v0) { float t=v0; v0=v1; v1=t; int q=i0; i0=i1; i1=q; }
            }
        }
        float e1 = __expf(v1 - v0);
        float e2 = __expf(v2 - v0);
        float e3 = __expf(v3 - v0);
        float e4 = __expf(v4 - v0);
        float inv = LAMBDA_ / (1.0f + e1 + e2 + e3 + e4);
        w5[tid*5+0] = inv;      i5[tid*5+0] = i0;
        w5[tid*5+1] = e1 * inv; i5[tid*5+1] = i1;
        w5[tid*5+2] = e2 * inv; i5[tid*5+2] = i2;
        w5[tid*5+3] = e3 * inv; i5[tid*5+3] = i3;
        w5[tid*5+4] = e4 * inv; i5[tid*5+4] = i4;
    }
    __syncthreads();

    // ================= phase 2: out = W @ C + x =================
    // zero Wh/Wl (0..61440)
    {
        uint4 z = make_uint4(0, 0, 0, 0);
        #pragma unroll
        for (int i = 0; i < 15; i++)
            *(uint4*)(smem + (tid * 15 + i) * 16) = z;
    }
    __syncthreads();
    // scatter weights
    if (tid < BM) {
        #pragma unroll
        for (int j = 0; j < 5; j++) {
            float wv = w5[tid * 5 + j];
            int   cj = i5[tid * 5 + j];
            __half hh = __float2half_rn(wv);
            __half hl = __float2half_rn(wv - __half2float(hh));
            *(__half*)(smem + WH_OFF + tid * W_STRIDE + cj * 2) = hh;
            *(__half*)(smem + WL_OFF + tid * W_STRIDE + cj * 2) = hl;
        }
    }
    __syncthreads();

    const uint32_t whOff = WH_OFF + (uint32_t)(mg * 32 + (l & 15)) * W_STRIDE + ((l >> 4) << 4);

    for (int c = 0; c < 8; c++) {
        CP_WAIT0();
        __syncthreads();
        if (c + 1 < 8) {
            const char* src = (const char*)g_b2 + (size_t)(c + 1) * B2_STAGE;
            uint32_t dst = sb + B2_OFF + ((c + 1) & 1) * B2_STAGE;
            #pragma unroll
            for (int i = 0; i < 4; i++) {
                int idx = tid + 256 * i;
                if (i < 3 || idx < 896)
                    CPASYNC16(dst + idx * 16, src + idx * 16);
            }
            CP_COMMIT();
        }

        float d2[2][4][4];
        #pragma unroll
        for (int m = 0; m < 2; m++)
            #pragma unroll
            for (int p = 0; p < 4; p++)
                #pragma unroll
                for (int j = 0; j < 4; j++) d2[m][p][j] = 0.0f;

        const uint2* B2s = (const uint2*)(smem + B2_OFF + (c & 1) * B2_STAGE);

        #pragma unroll
        for (int kh = 0; kh < 7; kh++) {
            uint32_t wh[2][4], wl[2][4];
            LDSM4(wh[0], sb + whOff + kh * 32);
            LDSM4(wh[1], sb + whOff + 16 * W_STRIDE + kh * 32);
            LDSM4(wl[0], sb + whOff + (WL_OFF - WH_OFF) + kh * 32);
            LDSM4(wl[1], sb + whOff + (WL_OFF - WH_OFF) + 16 * W_STRIDE + kh * 32);
            uint2 b[4];
            #pragma unroll
            for (int p = 0; p < 4; p++)
                b[p] = B2s[((kh * 8) + nh * 4 + p) * 32 + l];
            #pragma unroll
            for (int p = 0; p < 4; p++) {
                MMA(d2[0][p], wh[0], b[p].x, b[p].y);
                MMA(d2[1][p], wh[1], b[p].x, b[p].y);
                MMA(d2[0][p], wl[0], b[p].x, b[p].y);
                MMA(d2[1][p], wl[1], b[p].x, b[p].y);
            }
        }

        // fragment epilogue: out = d2 + x
        #pragma unroll
        for (int m = 0; m < 2; m++) {
            int r = row0 + mg * 32 + m * 16 + (l >> 2);
            #pragma unroll
            for (int p = 0; p < 4; p++) {
                int dd = c * 64 + nh * 32 + p * 8 + (l & 3) * 2;
                float2 xa = *(const float2*)&x[(size_t)r * D_DIM + dd];
                float2 xb = *(const float2*)&x[(size_t)(r + 8) * D_DIM + dd];
                float2 oa = make_float2(d2[m][p][0] + xa.x, d2[m][p][1] + xa.y);
                float2 ob = make_float2(d2[m][p][2] + xb.x, d2[m][p][3] + xb.y);
                *(float2*)&out[(size_t)r * D_DIM + dd]       = oa;
                *(float2*)&out[(size_t)(r + 8) * D_DIM + dd] = ob;
            }
        }
    }
}

extern "C" void kernel_launch(void* const* d_in, const int* in_sizes, int n_in,
                              void* d_out, int out_size)
{
    const float* x  = (const float*)d_in[0];
    const float* cc = (const float*)d_in[1];
    int B = in_sizes[0] / D_DIM;

    cc_frag_kernel<<<32 * 14, 32>>>(cc);
    cc_frag2_kernel<<<8 * 56, 32>>>(cc);

    cudaFuncSetAttribute(tse_hmma5_kernel, cudaFuncAttributeMaxDynamicSharedMemorySize, SMEM_BYTES);
    tse_hmma5_kernel<<<B / BM, NTHR, SMEM_BYTES>>>(x, cc, (float*)d_out);
}